// round 1
// baseline (speedup 1.0000x reference)
#include <cuda_runtime.h>
#include <math.h>

// AnchorKNNEncoder: for each (batch, side), find 4 nearest 2-D anchors out of
// M=8192, run a tiny 2->64->64 GELU MLP on them, softmax(d2/tau)-weighted sum.
// Fully fused: one CTA per (b, side). HBM-bound on the 512 MB anchor stream.

constexpr int EMBD = 64;
constexpr int MM   = 8192;
constexpr int NT   = 256;
constexpr float TAUF = 0.3f;

__device__ __forceinline__ bool better(float d, int i, float D, int I) {
    // strict-weak order matching lax.top_k stability: smaller d2 first,
    // ties broken by smaller index.
    return (d < D) || ((d == D) && (i < I));
}

__device__ __forceinline__ void insert4(float d, int i, float bd[4], int bi[4]) {
    if (better(d, i, bd[3], bi[3])) {
        bd[3] = d; bi[3] = i;
        if (better(bd[3], bi[3], bd[2], bi[2])) {
            float td = bd[2]; int ti = bi[2];
            bd[2] = bd[3]; bi[2] = bi[3]; bd[3] = td; bi[3] = ti;
        }
        if (better(bd[2], bi[2], bd[1], bi[1])) {
            float td = bd[1]; int ti = bi[1];
            bd[1] = bd[2]; bi[1] = bi[2]; bd[2] = td; bi[2] = ti;
        }
        if (better(bd[1], bi[1], bd[0], bi[0])) {
            float td = bd[0]; int ti = bi[0];
            bd[0] = bd[1]; bi[0] = bi[1]; bd[1] = td; bi[1] = ti;
        }
    }
}

__device__ __forceinline__ float gelu_exact(float x) {
    return 0.5f * x * (1.0f + erff(x * 0.70710678118654752440f));
}

__global__ __launch_bounds__(NT)
void anchor_knn_kernel(
    const float* __restrict__ nodes,   // (B, 2, 2)
    const float* __restrict__ ancS,    // (B, M, 2)
    const float* __restrict__ ancL,    // (B, M, 2)
    const float* __restrict__ W1,      // (64, 2)
    const float* __restrict__ b1,      // (64,)
    const float* __restrict__ W2,      // (64, 64)  [f, e]
    const float* __restrict__ b2,      // (64,)
    float* __restrict__ out,           // (2, B, 64): hs then hl
    int B)
{
    __shared__ float sd[4 * NT];         // top4 distances, [k*NT + tid] layout
    __shared__ int   si[4 * NT];         // top4 indices
    __shared__ float W2s[EMBD * 65];     // padded stride 65 -> conflict-free
    __shared__ float hsh[4][EMBD];
    __shared__ float osh[4][EMBD];

    const int b    = blockIdx.x;
    const int side = blockIdx.y;
    const int tid  = threadIdx.x;

    const float* __restrict__ A = (side ? ancL : ancS) + (size_t)b * (MM * 2);

    // Stage W2 into padded shared (L2-resident after first wave; 16 KB)
    for (int idx = tid; idx < EMBD * EMBD; idx += NT)
        W2s[(idx >> 6) * 65 + (idx & 63)] = W2[idx];

    const float x0 = nodes[b * 4 + side * 2 + 0];
    const float y0 = nodes[b * 4 + side * 2 + 1];

    float bd[4] = {INFINITY, INFINITY, INFINITY, INFINITY};
    int   bi[4] = {0x7fffffff, 0x7fffffff, 0x7fffffff, 0x7fffffff};

    // Stream anchors as float4 (two points per load). 16 iters per thread.
    const float4* __restrict__ A4 = reinterpret_cast<const float4*>(A);
    #pragma unroll 4
    for (int i = 0; i < (MM / 2) / NT; ++i) {
        const int    j = i * NT + tid;
        const float4 p = __ldg(&A4[j]);
        const int    m0 = 2 * j;
        float dx0 = p.x - x0, dy0 = p.y - y0;
        float d0  = dx0 * dx0 + dy0 * dy0;
        float dx1 = p.z - x0, dy1 = p.w - y0;
        float d1  = dx1 * dx1 + dy1 * dy1;
        insert4(d0, m0,     bd, bi);
        insert4(d1, m0 + 1, bd, bi);
    }

    #pragma unroll
    for (int k = 0; k < 4; ++k) { sd[k * NT + tid] = bd[k]; si[k * NT + tid] = bi[k]; }
    __syncthreads();

    // Tree merge: 256 sorted 4-lists -> 1 (8 levels)
    for (int s = NT / 2; s > 0; s >>= 1) {
        if (tid < s) {
            float md[4]; int mi[4];
            #pragma unroll
            for (int k = 0; k < 4; ++k) { md[k] = sd[k * NT + tid]; mi[k] = si[k * NT + tid]; }
            #pragma unroll
            for (int k = 0; k < 4; ++k)
                insert4(sd[k * NT + tid + s], si[k * NT + tid + s], md, mi);
            #pragma unroll
            for (int k = 0; k < 4; ++k) { sd[k * NT + tid] = md[k]; si[k * NT + tid] = mi[k]; }
        }
        __syncthreads();
    }

    // Final top-4 (ascending d2) now at slot tid==0
    float fd[4]; int fi[4];
    #pragma unroll
    for (int k = 0; k < 4; ++k) { fd[k] = sd[k * NT]; fi[k] = si[k * NT]; }

    // Softmax weights over logits d2/tau  (vals/-tau with vals = -d2)
    float lg[4];
    #pragma unroll
    for (int k = 0; k < 4; ++k) lg[k] = fd[k] * (1.0f / TAUF);
    float mx = fmaxf(fmaxf(lg[0], lg[1]), fmaxf(lg[2], lg[3]));
    float ex[4];
    float ssum = 0.0f;
    #pragma unroll
    for (int k = 0; k < 4; ++k) { ex[k] = expf(lg[k] - mx); ssum += ex[k]; }
    const float inv_sum = 1.0f / ssum;

    // MLP: thread (k, f) with k = tid>>6, f = tid&63
    const int k = tid >> 6;
    const int f = tid & 63;

    const float ax = A[fi[k] * 2 + 0];
    const float ay = A[fi[k] * 2 + 1];
    hsh[k][f] = gelu_exact(fmaf(ax, W1[f * 2 + 0], fmaf(ay, W1[f * 2 + 1], b1[f])));
    __syncthreads();

    float acc = b2[f];
    #pragma unroll
    for (int e = 0; e < EMBD; ++e)
        acc = fmaf(hsh[k][e], W2s[f * 65 + e], acc);
    osh[k][f] = gelu_exact(acc) * (ex[k] * inv_sum);
    __syncthreads();

    if (tid < EMBD) {
        out[((size_t)side * B + b) * EMBD + tid] =
            osh[0][tid] + osh[1][tid] + osh[2][tid] + osh[3][tid];
    }
}

extern "C" void kernel_launch(void* const* d_in, const int* in_sizes, int n_in,
                              void* d_out, int out_size) {
    const float* nodes = (const float*)d_in[0];
    const float* ancS  = (const float*)d_in[1];
    const float* ancL  = (const float*)d_in[2];
    const float* W1    = (const float*)d_in[3];
    const float* b1    = (const float*)d_in[4];
    const float* W2    = (const float*)d_in[5];
    const float* b2    = (const float*)d_in[6];

    const int B = in_sizes[0] / 4;   // nodes_2x2 is (B, 2, 2)

    dim3 grid(B, 2);
    anchor_knn_kernel<<<grid, NT>>>(nodes, ancS, ancL, W1, b1, W2, b2,
                                    (float*)d_out, B);
}

// round 2
// speedup vs baseline: 1.6504x; 1.6504x over previous
#include <cuda_runtime.h>
#include <math.h>
#include <limits.h>

// AnchorKNNEncoder, two-kernel fused pipeline.
// K1: per (b,side) CTA: stream 8192 2-D anchors, exact top-4 by squared
//     distance via branchless min-pass + threshold-filtered second pass
//     (from smem), softmax(d2/tau) weights, write coords+weights to scratch.
// K2: tiny 2->64->64 exact-GELU MLP + weighted sum over the 4 neighbors.

constexpr int   EMBD = 64;
constexpr int   MM   = 8192;
constexpr int   NT   = 256;    // kernel1 block
constexpr int   CAP  = 256;    // candidate buffer entries
constexpr int   UPC  = 8;      // units per CTA in kernel2
constexpr int   MAXB = 4096;
constexpr float TAUF = 0.3f;

__device__ float g_scr[2 * MAXB * 12];   // per unit: 4x(x,y) coords + 4 weights

// ---------- packed f32x2 helpers (sm_103a) ----------
__device__ __forceinline__ unsigned long long pk2(float a, float b) {
    unsigned long long r;
    asm("mov.b64 %0, {%1, %2};" : "=l"(r) : "f"(a), "f"(b));
    return r;
}
__device__ __forceinline__ void upk2(unsigned long long v, float& a, float& b) {
    asm("mov.b64 {%0, %1}, %2;" : "=f"(a), "=f"(b) : "l"(v));
}
__device__ __forceinline__ unsigned long long add2(unsigned long long a, unsigned long long b) {
    unsigned long long r; asm("add.rn.f32x2 %0, %1, %2;" : "=l"(r) : "l"(a), "l"(b)); return r;
}
__device__ __forceinline__ unsigned long long mul2(unsigned long long a, unsigned long long b) {
    unsigned long long r; asm("mul.rn.f32x2 %0, %1, %2;" : "=l"(r) : "l"(a), "l"(b)); return r;
}
__device__ __forceinline__ unsigned long long fma2(unsigned long long a, unsigned long long b, unsigned long long c) {
    unsigned long long r; asm("fma.rn.f32x2 %0, %1, %2, %3;" : "=l"(r) : "l"(a), "l"(b), "l"(c)); return r;
}

// ---------- stable (d, idx) ordering, matches lax.top_k ----------
__device__ __forceinline__ bool better(float d, int i, float D, int I) {
    return (d < D) || ((d == D) && (i < I));
}

__device__ __forceinline__ void insert4(float d, int i, float bd[4], int bi[4]) {
    if (better(d, i, bd[3], bi[3])) {
        bd[3] = d; bi[3] = i;
        if (better(bd[3], bi[3], bd[2], bi[2])) {
            float td = bd[2]; int ti = bi[2];
            bd[2] = bd[3]; bi[2] = bi[3]; bd[3] = td; bi[3] = ti;
        }
        if (better(bd[2], bi[2], bd[1], bi[1])) {
            float td = bd[1]; int ti = bi[1];
            bd[1] = bd[2]; bi[1] = bi[2]; bd[2] = td; bi[2] = ti;
        }
        if (better(bd[1], bi[1], bd[0], bi[0])) {
            float td = bd[0]; int ti = bi[0];
            bd[0] = bd[1]; bi[0] = bi[1]; bd[1] = td; bi[1] = ti;
        }
    }
}

__device__ __forceinline__ void cxp(float& d0, int& i0, float& d1, int& i1) {
    if (better(d1, i1, d0, i0)) {
        float td = d0; d0 = d1; d1 = td;
        int   ti = i0; i0 = i1; i1 = ti;
    }
}

__device__ __forceinline__ void cxf(float& a, float& b) {
    float lo = fminf(a, b), hi = fmaxf(a, b);
    a = lo; b = hi;
}

// branchless insert of v into ascending 4-list (distance only)
__device__ __forceinline__ void bl_insert4(float v, float& a0, float& a1, float& a2, float& a3) {
    float c;
    c  = fmaxf(a0, v); a0 = fminf(a0, v);
    float c1 = fmaxf(a1, c); a1 = fminf(a1, c); c = c1;
    float c2 = fmaxf(a2, c); a2 = fminf(a2, c); c = c2;
    a3 = fminf(a3, c);
}

// =====================================================================
// Kernel 1: exact top-4 per (b, side)
// =====================================================================
__global__ __launch_bounds__(NT)
void knn_kernel(const float* __restrict__ nodes,
                const float* __restrict__ ancS,
                const float* __restrict__ ancL,
                int B)
{
    __shared__ float s_d[MM];          // 32 KB of d2 values
    __shared__ float s_min[NT];        // per-thread minima
    __shared__ float s_thr;
    __shared__ int   s_cnt;
    __shared__ float s_cd[CAP];
    __shared__ int   s_ci[CAP];

    const int b    = blockIdx.x;
    const int side = blockIdx.y;
    const int tid  = threadIdx.x;

    const float* __restrict__ A = (side ? ancL : ancS) + (size_t)b * (MM * 2);

    if (tid == 0) s_cnt = 0;

    const float x0 = nodes[b * 4 + side * 2 + 0];
    const float y0 = nodes[b * 4 + side * 2 + 1];
    const unsigned long long ncx = pk2(-x0, -x0);
    const unsigned long long ncy = pk2(-y0, -y0);

    // ---- Pass A: stream, compute d2, store to smem, track per-thread min ----
    const float4* __restrict__ A4 = reinterpret_cast<const float4*>(A);
    float2* s_d2 = reinterpret_cast<float2*>(s_d);
    float vmin = INFINITY;

    #pragma unroll 4
    for (int i = 0; i < (MM / 2) / (2 * NT); ++i) {   // 8 iters, 2 float4 each
        const int j0 = i * (2 * NT) + tid;
        const int j1 = j0 + NT;
        const float4 p = A4[j0];
        const float4 q = A4[j1];

        unsigned long long dxp = add2(pk2(p.x, p.z), ncx);
        unsigned long long dyp = add2(pk2(p.y, p.w), ncy);
        unsigned long long ddp = fma2(dyp, dyp, mul2(dxp, dxp));
        unsigned long long dxq = add2(pk2(q.x, q.z), ncx);
        unsigned long long dyq = add2(pk2(q.y, q.w), ncy);
        unsigned long long ddq = fma2(dyq, dyq, mul2(dxq, dxq));

        float d0, d1, d2, d3;
        upk2(ddp, d0, d1);
        upk2(ddq, d2, d3);
        s_d2[j0] = make_float2(d0, d1);
        s_d2[j1] = make_float2(d2, d3);
        vmin = fminf(vmin, fminf(fminf(d0, d1), fminf(d2, d3)));
    }
    s_min[tid] = vmin;
    __syncthreads();

    // ---- threshold = 4th smallest of the 256 thread-minima (warp 0) ----
    if (tid < 32) {
        float a0 = INFINITY, a1 = INFINITY, a2 = INFINITY, a3 = INFINITY;
        #pragma unroll
        for (int r = 0; r < NT / 32; ++r)
            bl_insert4(s_min[tid + r * 32], a0, a1, a2, a3);
        #pragma unroll
        for (int off = 16; off > 0; off >>= 1) {
            float b0 = __shfl_xor_sync(0xffffffffu, a0, off);
            float b1 = __shfl_xor_sync(0xffffffffu, a1, off);
            float b2 = __shfl_xor_sync(0xffffffffu, a2, off);
            float b3 = __shfl_xor_sync(0xffffffffu, a3, off);
            // bitonic lowest-4 of two ascending 4-lists
            float t0 = fminf(a0, b3), t1 = fminf(a1, b2);
            float t2 = fminf(a2, b1), t3 = fminf(a3, b0);
            cxf(t0, t2); cxf(t1, t3); cxf(t0, t1); cxf(t2, t3);
            a0 = t0; a1 = t1; a2 = t2; a3 = t3;
        }
        if (tid == 0) s_thr = a3;
    }
    __syncthreads();

    // ---- Pass B: rescan from smem against threshold, collect candidates ----
    const float thr = s_thr;
    const float4* s_d4 = reinterpret_cast<const float4*>(s_d);
    #pragma unroll
    for (int i = 0; i < (MM / 4) / (2 * NT); ++i) {   // 4 iters, 8 pts each
        const int v0 = i * (2 * NT) + tid;
        const int v1 = v0 + NT;
        const float4 p = s_d4[v0];
        const float4 q = s_d4[v1];
        const float m = fminf(fminf(fminf(p.x, p.y), fminf(p.z, p.w)),
                              fminf(fminf(q.x, q.y), fminf(q.z, q.w)));
        if (m <= thr) {
            const float ds[8] = {p.x, p.y, p.z, p.w, q.x, q.y, q.z, q.w};
            const int   bs[8] = {4*v0, 4*v0+1, 4*v0+2, 4*v0+3,
                                 4*v1, 4*v1+1, 4*v1+2, 4*v1+3};
            #pragma unroll
            for (int r = 0; r < 8; ++r) {
                if (ds[r] <= thr) {
                    int pos = atomicAdd(&s_cnt, 1);
                    if (pos < CAP) { s_cd[pos] = ds[r]; s_ci[pos] = bs[r]; }
                }
            }
        }
    }
    __syncthreads();

    // ---- exact stable top-4 over candidates (warp 0), softmax, emit ----
    if (tid < 32) {
        const int n = min(s_cnt, CAP);
        float fd[4] = {INFINITY, INFINITY, INFINITY, INFINITY};
        int   fi[4] = {INT_MAX, INT_MAX, INT_MAX, INT_MAX};
        for (int c = tid; c < n; c += 32)
            insert4(s_cd[c], s_ci[c], fd, fi);

        #pragma unroll
        for (int off = 16; off > 0; off >>= 1) {
            float bd_[4]; int bi_[4];
            #pragma unroll
            for (int k = 0; k < 4; ++k) {
                bd_[k] = __shfl_xor_sync(0xffffffffu, fd[k], off);
                bi_[k] = __shfl_xor_sync(0xffffffffu, fi[k], off);
            }
            float t0, t1, t2, t3; int u0, u1, u2, u3;
            if (better(bd_[3], bi_[3], fd[0], fi[0])) { t0 = bd_[3]; u0 = bi_[3]; } else { t0 = fd[0]; u0 = fi[0]; }
            if (better(bd_[2], bi_[2], fd[1], fi[1])) { t1 = bd_[2]; u1 = bi_[2]; } else { t1 = fd[1]; u1 = fi[1]; }
            if (better(bd_[1], bi_[1], fd[2], fi[2])) { t2 = bd_[1]; u2 = bi_[1]; } else { t2 = fd[2]; u2 = fi[2]; }
            if (better(bd_[0], bi_[0], fd[3], fi[3])) { t3 = bd_[0]; u3 = bi_[0]; } else { t3 = fd[3]; u3 = fi[3]; }
            cxp(t0, u0, t2, u2); cxp(t1, u1, t3, u3);
            cxp(t0, u0, t1, u1); cxp(t2, u2, t3, u3);
            fd[0] = t0; fi[0] = u0; fd[1] = t1; fi[1] = u1;
            fd[2] = t2; fi[2] = u2; fd[3] = t3; fi[3] = u3;
        }

        if (tid < 4) {
            // softmax over logits d2/tau (vals/-tau with vals=-d2)
            float lg[4];
            #pragma unroll
            for (int k = 0; k < 4; ++k) lg[k] = fd[k] * (1.0f / TAUF);
            const float mx = fmaxf(fmaxf(lg[0], lg[1]), fmaxf(lg[2], lg[3]));
            float ssum = 0.0f, ex[4];
            #pragma unroll
            for (int k = 0; k < 4; ++k) { ex[k] = expf(lg[k] - mx); ssum += ex[k]; }
            const float w = ex[tid] / ssum;

            const size_t u = (size_t)side * B + b;
            const int id = fi[tid];
            g_scr[u * 12 + 2 * tid + 0] = A[2 * id + 0];
            g_scr[u * 12 + 2 * tid + 1] = A[2 * id + 1];
            g_scr[u * 12 + 8 + tid]     = w;
        }
    }
}

// =====================================================================
// Kernel 2: 2 -> 64 -> 64 exact-GELU MLP + weighted sum
// =====================================================================
__device__ __forceinline__ float gelu_exact(float x) {
    return 0.5f * x * (1.0f + erff(x * 0.70710678118654752440f));
}

__global__ __launch_bounds__(256)
void mlp_kernel(const float* __restrict__ W1, const float* __restrict__ b1,
                const float* __restrict__ W2, const float* __restrict__ b2,
                float* __restrict__ out, int nunits)
{
    __shared__ float W2s[EMBD * 65];   // padded: conflict-free f-indexed reads
    __shared__ float hsh[4][EMBD];
    __shared__ float osh[4][EMBD];

    const int tid = threadIdx.x;
    for (int idx = tid; idx < EMBD * EMBD; idx += 256)
        W2s[(idx >> 6) * 65 + (idx & 63)] = W2[idx];

    const int k = tid >> 6;
    const int f = tid & 63;
    const float w1a = W1[f * 2 + 0];
    const float w1b = W1[f * 2 + 1];
    const float bb1 = b1[f];
    const float bb2 = b2[f];
    __syncthreads();

    const int u_end = min(blockIdx.x * UPC + UPC, nunits);
    for (int u = blockIdx.x * UPC; u < u_end; ++u) {
        const float* s = g_scr + (size_t)u * 12;
        const float ax = s[2 * k + 0];
        const float ay = s[2 * k + 1];
        const float w  = s[8 + k];

        hsh[k][f] = gelu_exact(fmaf(ax, w1a, fmaf(ay, w1b, bb1)));
        __syncthreads();

        float acc = bb2;
        #pragma unroll
        for (int e = 0; e < EMBD; ++e)
            acc = fmaf(hsh[k][e], W2s[f * 65 + e], acc);
        osh[k][f] = gelu_exact(acc) * w;
        __syncthreads();

        if (tid < EMBD)
            out[(size_t)u * EMBD + tid] =
                osh[0][tid] + osh[1][tid] + osh[2][tid] + osh[3][tid];
        // safe to proceed: osh rewritten only after next __syncthreads()
    }
}

extern "C" void kernel_launch(void* const* d_in, const int* in_sizes, int n_in,
                              void* d_out, int out_size) {
    const float* nodes = (const float*)d_in[0];
    const float* ancS  = (const float*)d_in[1];
    const float* ancL  = (const float*)d_in[2];
    const float* W1    = (const float*)d_in[3];
    const float* b1    = (const float*)d_in[4];
    const float* W2    = (const float*)d_in[5];
    const float* b2    = (const float*)d_in[6];

    const int B = in_sizes[0] / 4;       // nodes_2x2 is (B, 2, 2)
    const int nunits = 2 * B;

    dim3 grid1(B, 2);
    knn_kernel<<<grid1, NT>>>(nodes, ancS, ancL, B);

    dim3 grid2((nunits + UPC - 1) / UPC);
    mlp_kernel<<<grid2, 256>>>(W1, b1, W2, b2, (float*)d_out, nunits);
}

// round 13
// speedup vs baseline: 2.1554x; 1.3060x over previous
#include <cuda_runtime.h>
#include <math.h>
#include <limits.h>

// AnchorKNNEncoder, two-kernel pipeline.
// K1: per (b,side) CTA: stream 8192 2-D anchors (register-resident d2),
//     exact top-4 via branchless min pass + threshold-filtered register
//     rescan, softmax(d2/tau) weights, coords+weights -> scratch.
// K2: 2->64->64 exact-GELU MLP, 64 threads per unit, broadcast-vectorized.

constexpr int   EMBD = 64;
constexpr int   MM   = 8192;
constexpr int   NT   = 256;    // kernel1 block
constexpr int   CAP  = 256;    // candidate buffer entries
constexpr int   UPC  = 8;      // units per CTA in kernel2 (must divide 2B)
constexpr int   MAXB = 4096;
constexpr float TAUF = 0.3f;

__device__ float g_scr[2 * MAXB * 12];   // per unit: 4x(x,y) coords + 4 weights

// ---------- packed f32x2 helpers (sm_103a) ----------
__device__ __forceinline__ unsigned long long pk2(float a, float b) {
    unsigned long long r;
    asm("mov.b64 %0, {%1, %2};" : "=l"(r) : "f"(a), "f"(b));
    return r;
}
__device__ __forceinline__ void upk2(unsigned long long v, float& a, float& b) {
    asm("mov.b64 {%0, %1}, %2;" : "=f"(a), "=f"(b) : "l"(v));
}
__device__ __forceinline__ unsigned long long add2(unsigned long long a, unsigned long long b) {
    unsigned long long r; asm("add.rn.f32x2 %0, %1, %2;" : "=l"(r) : "l"(a), "l"(b)); return r;
}
__device__ __forceinline__ unsigned long long mul2(unsigned long long a, unsigned long long b) {
    unsigned long long r; asm("mul.rn.f32x2 %0, %1, %2;" : "=l"(r) : "l"(a), "l"(b)); return r;
}
__device__ __forceinline__ unsigned long long fma2(unsigned long long a, unsigned long long b, unsigned long long c) {
    unsigned long long r; asm("fma.rn.f32x2 %0, %1, %2, %3;" : "=l"(r) : "l"(a), "l"(b), "l"(c)); return r;
}

// ---------- stable (d, idx) ordering, matches lax.top_k ----------
__device__ __forceinline__ bool better(float d, int i, float D, int I) {
    return (d < D) || ((d == D) && (i < I));
}

__device__ __forceinline__ void insert4(float d, int i, float bd[4], int bi[4]) {
    if (better(d, i, bd[3], bi[3])) {
        bd[3] = d; bi[3] = i;
        if (better(bd[3], bi[3], bd[2], bi[2])) {
            float td = bd[2]; int ti = bi[2];
            bd[2] = bd[3]; bi[2] = bi[3]; bd[3] = td; bi[3] = ti;
        }
        if (better(bd[2], bi[2], bd[1], bi[1])) {
            float td = bd[1]; int ti = bi[1];
            bd[1] = bd[2]; bi[1] = bi[2]; bd[2] = td; bi[2] = ti;
        }
        if (better(bd[1], bi[1], bd[0], bi[0])) {
            float td = bd[0]; int ti = bi[0];
            bd[0] = bd[1]; bi[0] = bi[1]; bd[1] = td; bi[1] = ti;
        }
    }
}

__device__ __forceinline__ void cxp(float& d0, int& i0, float& d1, int& i1) {
    if (better(d1, i1, d0, i0)) {
        float td = d0; d0 = d1; d1 = td;
        int   ti = i0; i0 = i1; i1 = ti;
    }
}

__device__ __forceinline__ void cxf(float& a, float& b) {
    float lo = fminf(a, b), hi = fmaxf(a, b);
    a = lo; b = hi;
}

// branchless insert of v into ascending 4-list (distance only)
__device__ __forceinline__ void bl_insert4(float v, float& a0, float& a1, float& a2, float& a3) {
    float c;
    c  = fmaxf(a0, v); a0 = fminf(a0, v);
    float c1 = fmaxf(a1, c); a1 = fminf(a1, c); c = c1;
    float c2 = fmaxf(a2, c); a2 = fminf(a2, c); c = c2;
    a3 = fminf(a3, c);
}

// =====================================================================
// Kernel 1: exact top-4 per (b, side), register-resident d2
// =====================================================================
__global__ __launch_bounds__(NT)
void knn_kernel(const float* __restrict__ nodes,
                const float* __restrict__ ancS,
                const float* __restrict__ ancL,
                int B)
{
    __shared__ float s_min[NT];
    __shared__ float s_thr;
    __shared__ int   s_cnt;
    __shared__ float s_cd[CAP];
    __shared__ int   s_ci[CAP];

    const int b    = blockIdx.x;
    const int side = blockIdx.y;
    const int tid  = threadIdx.x;

    const float* __restrict__ A = (side ? ancL : ancS) + (size_t)b * (MM * 2);

    if (tid == 0) s_cnt = 0;

    const float x0 = nodes[b * 4 + side * 2 + 0];
    const float y0 = nodes[b * 4 + side * 2 + 1];
    const unsigned long long ncx = pk2(-x0, -x0);
    const unsigned long long ncy = pk2(-y0, -y0);

    // ---- Pass A: stream anchors, keep all 32 d2 in registers ----
    const float4* __restrict__ A4 = reinterpret_cast<const float4*>(A);
    float d2r[MM / NT];                 // 32 floats
    float vmin = INFINITY;

    #pragma unroll
    for (int o = 0; o < 4; ++o) {       // 4 batches x 4 float4 loads
        float4 pp[4];
        #pragma unroll
        for (int t = 0; t < 4; ++t)
            pp[t] = __ldcs(&A4[(o * 4 + t) * NT + tid]);
        #pragma unroll
        for (int t = 0; t < 4; ++t) {
            unsigned long long dx = add2(pk2(pp[t].x, pp[t].z), ncx);
            unsigned long long dy = add2(pk2(pp[t].y, pp[t].w), ncy);
            unsigned long long dd = fma2(dy, dy, mul2(dx, dx));
            float da, db;
            upk2(dd, da, db);
            d2r[(o * 4 + t) * 2 + 0] = da;
            d2r[(o * 4 + t) * 2 + 1] = db;
            vmin = fminf(vmin, fminf(da, db));
        }
    }
    s_min[tid] = vmin;
    __syncthreads();

    // ---- threshold = 4th smallest of the 256 thread-minima (warp 0) ----
    if (tid < 32) {
        float a0 = INFINITY, a1 = INFINITY, a2 = INFINITY, a3 = INFINITY;
        #pragma unroll
        for (int r = 0; r < NT / 32; ++r)
            bl_insert4(s_min[tid + r * 32], a0, a1, a2, a3);
        #pragma unroll
        for (int off = 16; off > 0; off >>= 1) {
            float b0 = __shfl_xor_sync(0xffffffffu, a0, off);
            float b1 = __shfl_xor_sync(0xffffffffu, a1, off);
            float b2 = __shfl_xor_sync(0xffffffffu, a2, off);
            float b3 = __shfl_xor_sync(0xffffffffu, a3, off);
            float t0 = fminf(a0, b3), t1 = fminf(a1, b2);
            float t2 = fminf(a2, b1), t3 = fminf(a3, b0);
            cxf(t0, t2); cxf(t1, t3); cxf(t0, t1); cxf(t2, t3);
            a0 = t0; a1 = t1; a2 = t2; a3 = t3;
        }
        if (tid == 0) s_thr = a3;
    }
    __syncthreads();

    // ---- Pass B: rescan registers against threshold ----
    const float thr = s_thr;
    #pragma unroll
    for (int t = 0; t < MM / (2 * NT); ++t) {     // 16 pairs
        const float da = d2r[2 * t + 0];
        const float db = d2r[2 * t + 1];
        if (fminf(da, db) <= thr) {
            const int j = t * NT + tid;           // float4 slot -> pts 2j, 2j+1
            if (da <= thr) {
                int pos = atomicAdd(&s_cnt, 1);
                if (pos < CAP) { s_cd[pos] = da; s_ci[pos] = 2 * j; }
            }
            if (db <= thr) {
                int pos = atomicAdd(&s_cnt, 1);
                if (pos < CAP) { s_cd[pos] = db; s_ci[pos] = 2 * j + 1; }
            }
        }
    }
    __syncthreads();

    // ---- exact stable top-4 over candidates (warp 0), softmax, emit ----
    if (tid < 32) {
        const int n = min(s_cnt, CAP);
        float fd[4] = {INFINITY, INFINITY, INFINITY, INFINITY};
        int   fi[4] = {INT_MAX, INT_MAX, INT_MAX, INT_MAX};
        for (int c = tid; c < n; c += 32)
            insert4(s_cd[c], s_ci[c], fd, fi);

        #pragma unroll
        for (int off = 16; off > 0; off >>= 1) {
            float bd_[4]; int bi_[4];
            #pragma unroll
            for (int k = 0; k < 4; ++k) {
                bd_[k] = __shfl_xor_sync(0xffffffffu, fd[k], off);
                bi_[k] = __shfl_xor_sync(0xffffffffu, fi[k], off);
            }
            float t0, t1, t2, t3; int u0, u1, u2, u3;
            if (better(bd_[3], bi_[3], fd[0], fi[0])) { t0 = bd_[3]; u0 = bi_[3]; } else { t0 = fd[0]; u0 = fi[0]; }
            if (better(bd_[2], bi_[2], fd[1], fi[1])) { t1 = bd_[2]; u1 = bi_[2]; } else { t1 = fd[1]; u1 = fi[1]; }
            if (better(bd_[1], bi_[1], fd[2], fi[2])) { t2 = bd_[1]; u2 = bi_[1]; } else { t2 = fd[2]; u2 = fi[2]; }
            if (better(bd_[0], bi_[0], fd[3], fi[3])) { t3 = bd_[0]; u3 = bi_[0]; } else { t3 = fd[3]; u3 = fi[3]; }
            cxp(t0, u0, t2, u2); cxp(t1, u1, t3, u3);
            cxp(t0, u0, t1, u1); cxp(t2, u2, t3, u3);
            fd[0] = t0; fi[0] = u0; fd[1] = t1; fi[1] = u1;
            fd[2] = t2; fi[2] = u2; fd[3] = t3; fi[3] = u3;
        }

        if (tid < 4) {
            float lg[4];
            #pragma unroll
            for (int k = 0; k < 4; ++k) lg[k] = fd[k] * (1.0f / TAUF);
            const float mx = fmaxf(fmaxf(lg[0], lg[1]), fmaxf(lg[2], lg[3]));
            float ssum = 0.0f, ex[4];
            #pragma unroll
            for (int k = 0; k < 4; ++k) { ex[k] = expf(lg[k] - mx); ssum += ex[k]; }
            const float w = ex[tid] / ssum;

            const size_t u = (size_t)side * B + b;
            const int id = fi[tid];
            g_scr[u * 12 + 2 * tid + 0] = A[2 * id + 0];
            g_scr[u * 12 + 2 * tid + 1] = A[2 * id + 1];
            g_scr[u * 12 + 8 + tid]     = w;
        }
    }
}

// =====================================================================
// Kernel 2: 2 -> 64 -> 64 exact-GELU MLP, 64 threads per unit
// =====================================================================
__device__ __forceinline__ float gelu_exact(float x) {
    return 0.5f * x * (1.0f + erff(x * 0.70710678118654752440f));
}

constexpr int W2STRIDE = 68;   // float4-aligned, conflict-free per phase

__global__ __launch_bounds__(256)
void mlp_kernel(const float* __restrict__ W1, const float* __restrict__ b1,
                const float* __restrict__ W2, const float* __restrict__ b2,
                float* __restrict__ out, int nunits)
{
    __shared__ float W2s[EMBD * W2STRIDE];
    __shared__ float hsh[4][EMBD][4];    // [group][e][k], float4 per (g,e)

    const int tid = threadIdx.x;
    for (int idx = tid; idx < EMBD * EMBD; idx += 256)
        W2s[(idx >> 6) * W2STRIDE + (idx & 63)] = W2[idx];

    const int g = tid >> 6;      // group = unit within chunk
    const int f = tid & 63;      // output feature
    const float w1a = W1[f * 2 + 0];
    const float w1b = W1[f * 2 + 1];
    const float bb1 = b1[f];
    const float bb2 = b2[f];
    __syncthreads();

    for (int c = 0; c < UPC / 4; ++c) {
        const int u = blockIdx.x * UPC + c * 4 + g;
        const float* s = g_scr + (size_t)u * 12;

        float wk[4];
        float4 hv;
        {
            float h0 = gelu_exact(fmaf(s[0], w1a, fmaf(s[1], w1b, bb1)));
            float h1 = gelu_exact(fmaf(s[2], w1a, fmaf(s[3], w1b, bb1)));
            float h2 = gelu_exact(fmaf(s[4], w1a, fmaf(s[5], w1b, bb1)));
            float h3 = gelu_exact(fmaf(s[6], w1a, fmaf(s[7], w1b, bb1)));
            hv = make_float4(h0, h1, h2, h3);
            wk[0] = s[8]; wk[1] = s[9]; wk[2] = s[10]; wk[3] = s[11];
        }
        *reinterpret_cast<float4*>(&hsh[g][f][0]) = hv;
        __syncthreads();

        float acc0 = bb2, acc1 = bb2, acc2 = bb2, acc3 = bb2;
        #pragma unroll
        for (int e = 0; e < EMBD; e += 4) {
            const float4 w2 = *reinterpret_cast<const float4*>(&W2s[f * W2STRIDE + e]);
            const float4 h0 = *reinterpret_cast<const float4*>(&hsh[g][e + 0][0]);
            const float4 h1 = *reinterpret_cast<const float4*>(&hsh[g][e + 1][0]);
            const float4 h2 = *reinterpret_cast<const float4*>(&hsh[g][e + 2][0]);
            const float4 h3 = *reinterpret_cast<const float4*>(&hsh[g][e + 3][0]);
            acc0 = fmaf(h0.x, w2.x, fmaf(h1.x, w2.y, fmaf(h2.x, w2.z, fmaf(h3.x, w2.w, acc0))));
            acc1 = fmaf(h0.y, w2.x, fmaf(h1.y, w2.y, fmaf(h2.y, w2.z, fmaf(h3.y, w2.w, acc1))));
            acc2 = fmaf(h0.z, w2.x, fmaf(h1.z, w2.y, fmaf(h2.z, w2.z, fmaf(h3.z, w2.w, acc2))));
            acc3 = fmaf(h0.w, w2.x, fmaf(h1.w, w2.y, fmaf(h2.w, w2.z, fmaf(h3.w, w2.w, acc3))));
        }

        out[(size_t)u * EMBD + f] =
            gelu_exact(acc0) * wk[0] + gelu_exact(acc1) * wk[1] +
            gelu_exact(acc2) * wk[2] + gelu_exact(acc3) * wk[3];
        __syncthreads();   // hsh reused next chunk
    }
}

extern "C" void kernel_launch(void* const* d_in, const int* in_sizes, int n_in,
                              void* d_out, int out_size) {
    const float* nodes = (const float*)d_in[0];
    const float* ancS  = (const float*)d_in[1];
    const float* ancL  = (const float*)d_in[2];
    const float* W1    = (const float*)d_in[3];
    const float* b1    = (const float*)d_in[4];
    const float* W2    = (const float*)d_in[5];
    const float* b2    = (const float*)d_in[6];

    const int B = in_sizes[0] / 4;       // nodes_2x2 is (B, 2, 2)
    const int nunits = 2 * B;            // 8192; divisible by UPC

    dim3 grid1(B, 2);
    knn_kernel<<<grid1, NT>>>(nodes, ancS, ancL, B);

    dim3 grid2(nunits / UPC);
    mlp_kernel<<<grid2, 256>>>(W1, b1, W2, b2, (float*)d_out, nunits);
}